// round 14
// baseline (speedup 1.0000x reference)
#include <cuda_runtime.h>
#include <cstdint>

// UnalignmentLoss: min over 17x17 shifts (step 2) of mean L1 between shifted
// x crop and fixed y center crop. x,y: (4,3,256,256) fp32, crop 224x224.
//
// j-split design: blockIdx.y in [0,34) encodes (shift-row i, j-half jb).
// Each warp handles 28 rows and HALF the column shifts (9 or 8), so packed
// f32x2 accumulators fit (18 regs) and the x window is only 12 pairs
// (6 LDS.128/row). x,y staged GMEM->SMEM via cp.async double buffers with
// swizzled conflict-free access. Math per j: 4 FFMA2 + 8 LOP3 + 4 ADD2.
// Last block (atomic counter) does the 289-way min and resets state.
// (Resubmission of R13 source — previous round died to a broker infra failure.)

#define NS    17
#define W_    256
#define TOLC  16
#define COUNT_F 602112.0f          // 4*3*224*224
#define RPW   28                   // rows per warp
#define NBLOCKS (2 * 34 * 12)      // 816

__device__ float g_acc[NS * NS];   // zero at load; last block restores 0
__device__ unsigned g_count;       // zero at load; last block restores 0

// ---- packed f32x2 helpers (uint64_t = b64 carrier) ----
__device__ __forceinline__ uint64_t f2add(uint64_t a, uint64_t b) {
    uint64_t r; asm("add.rn.f32x2 %0, %1, %2;" : "=l"(r) : "l"(a), "l"(b)); return r;
}
__device__ __forceinline__ uint64_t f2fma(uint64_t a, uint64_t b, uint64_t c) {
    uint64_t r; asm("fma.rn.f32x2 %0, %1, %2, %3;" : "=l"(r) : "l"(a), "l"(b), "l"(c)); return r;
}
__device__ __forceinline__ uint64_t f2abs(uint64_t a) {
    return a & 0x7FFFFFFF7FFFFFFFULL;
}
__device__ __forceinline__ void unpack2(uint64_t v, float& lo, float& hi) {
    asm("mov.b64 {%0, %1}, %2;" : "=f"(lo), "=f"(hi) : "l"(v));
}
__device__ __forceinline__ void lds_2b64(unsigned addr, uint64_t& a, uint64_t& b) {
    asm volatile("ld.shared.v2.b64 {%0,%1}, [%2];" : "=l"(a), "=l"(b) : "r"(addr));
}
__device__ __forceinline__ void cp16(unsigned saddr, const float* g) {
    asm volatile("cp.async.ca.shared.global [%0], [%1], 16;"
                 :: "r"(saddr), "l"(g) : "memory");
}
__device__ __forceinline__ void cp_commit() {
    asm volatile("cp.async.commit_group;" ::: "memory");
}
template <int N>
__device__ __forceinline__ void cp_wait() {
    asm volatile("cp.async.wait_group %0;" :: "n"(N) : "memory");
}
// XOR swizzle on 16B granule index (row = 64 granules): conflict-free for the
// 2-granule staging copies and the strided window reads.
__device__ __forceinline__ int swz(int t) { return t ^ ((t >> 3) & 7); }

#define NEG1_X2 0xBF800000BF800000ULL   // packed (-1.0f, -1.0f)

// Mainloop for one j-half. JB=0: j=0..8 (window pairs 0..11, granules 0..5).
// JB=1: j=9..16 (window pairs 8..19, granules 4..9). Local wd slot = j - 8*JB.
template <int JB>
__device__ __forceinline__ void run_half(const float* xb, const float* yb,
                                         int i, int r0,
                                         unsigned xbase, unsigned ybase,
                                         unsigned s0, unsigned s1,
                                         int lane, float* accout) {
    constexpr int NJ = JB ? 8 : 9;

    const int Lc = lane < 28 ? lane : 27;          // idle lanes: broadcast reads
    unsigned roff[6];
#pragma unroll
    for (int m = 0; m < 6; m++)
        roff[m] = (unsigned)(swz(2 * Lc + 4 * JB + m) * 16);

    uint64_t acc[NJ];
#pragma unroll
    for (int jj = 0; jj < NJ; jj++) acc[jj] = 0ull;

    // Prologue: async-copy x and y row 0 into buffer 0.
    {
        const float* xr = xb + (size_t)(2 * i + r0) * W_ + 8 * lane;
        cp16(xbase + s0, xr);
        cp16(xbase + s1, xr + 4);
        const float* yr = yb + (size_t)(TOLC + r0) * W_ + TOLC + 8 * lane;
        cp16(ybase + s0, yr);       // lanes 28-31 stage don't-care (in-bounds)
        cp16(ybase + s1, yr + 4);
        cp_commit();
    }

#pragma unroll 1
    for (int rr = 0; rr < RPW; rr++) {
        const unsigned boff  = (rr & 1) ? (unsigned)(W_ * 4) : 0u;
        const unsigned nboff = boff ^ (unsigned)(W_ * 4);

        // Prefetch row rr+1 (clamped dup on last iter; harmless, in-bounds).
        const int rn = (rr < RPW - 1) ? rr + 1 : rr;
        const float* xn = xb + (size_t)(2 * i + r0 + rn) * W_ + 8 * lane;
        cp16(xbase + nboff + s0, xn);
        cp16(xbase + nboff + s1, xn + 4);
        const float* yn = yb + (size_t)(TOLC + r0 + rn) * W_ + TOLC + 8 * lane;
        cp16(ybase + nboff + s0, yn);
        cp16(ybase + nboff + s1, yn + 4);
        cp_commit();

        cp_wait<1>();       // row rr landed (only row rr+1 still in flight)
        __syncwarp();

        // y pairs for this lane's 8 columns (same swizzled slots it staged).
        uint64_t y0, y1, y2, y3;
        lds_2b64(ybase + boff + s0, y0, y1);
        lds_2b64(ybase + boff + s1, y2, y3);

        // x window: 6 granules = 12 pairs, one straight-line batch.
        uint64_t wd[12];
#pragma unroll
        for (int m = 0; m < 6; m++)
            lds_2b64(xbase + boff + roff[m], wd[2 * m], wd[2 * m + 1]);

#pragma unroll
        for (int jj = 0; jj < NJ; jj++) {
            const int p = jj + JB;      // local slot of pair (j - 8*JB)
            uint64_t a0 = f2abs(f2fma(y0, NEG1_X2, wd[p + 0]));  // |x - y|
            uint64_t a1 = f2abs(f2fma(y1, NEG1_X2, wd[p + 1]));
            uint64_t a2 = f2abs(f2fma(y2, NEG1_X2, wd[p + 2]));
            uint64_t a3 = f2abs(f2fma(y3, NEG1_X2, wd[p + 3]));
            acc[jj] = f2add(acc[jj], f2add(f2add(a0, a1), f2add(a2, a3)));
        }
    }
    cp_wait<0>();   // drain the dup prefetch before smem is released

#pragma unroll
    for (int jj = 0; jj < NJ; jj++) {
        float lo, hi; unpack2(acc[jj], lo, hi);
        accout[jj] = lo + hi;
    }
}

__global__ __launch_bounds__(128, 6) void corr_kernel(const float* __restrict__ x,
                                                      const float* __restrict__ y,
                                                      float* __restrict__ out) {
    const int warp = threadIdx.x >> 5;
    const int lane = threadIdx.x & 31;
    const int bc   = blockIdx.z;            // plane
    const int i    = blockIdx.y % NS;       // shift-row index (shift = 2*i)
    const int jb   = blockIdx.y / NS;       // j-half selector
    const int r0   = blockIdx.x * (4 * RPW) + warp * RPW;

    const float* xb = x + (size_t)bc * (W_ * W_);
    const float* yb = y + (size_t)bc * (W_ * W_);

    __shared__ __align__(16) float xs[4][2][W_];   // [warp][double-buffer][256]
    __shared__ __align__(16) float ys[4][2][W_];   // y crop rows (224 used)
    __shared__ unsigned s_last;

    const unsigned xbase = (unsigned)__cvta_generic_to_shared(&xs[warp][0][0]);
    const unsigned ybase = (unsigned)__cvta_generic_to_shared(&ys[warp][0][0]);
    const unsigned s0 = (unsigned)(swz(2 * lane)     * 16);
    const unsigned s1 = (unsigned)(swz(2 * lane + 1) * 16);

    float accs[9];
    if (jb == 0)
        run_half<0>(xb, yb, i, r0, xbase, ybase, s0, s1, lane, accs);
    else
        run_half<1>(xb, yb, i, r0, xbase, ybase, s0, s1, lane, accs);

    const int NJ  = jb ? 8 : 9;
    const int JLO = jb ? 9 : 0;

    // Reduce: lane jj keeps shift-column (JLO+jj)'s warp sum; idle lanes give 0.
    float keep = 0.0f;
#pragma unroll
    for (int jj = 0; jj < 9; jj++) {
        if (jj < NJ) {
            float v = (lane < 28) ? accs[jj] : 0.0f;
#pragma unroll
            for (int off = 16; off; off >>= 1)
                v += __shfl_xor_sync(0xffffffffu, v, off);
            if (lane == jj) keep = v;
        }
    }
    if (lane < NJ) atomicAdd(&g_acc[i * NS + JLO + lane], keep);

    // ---- last-block finalize (threadFenceReduction pattern) ----
    __threadfence();
    if (threadIdx.x == 0) {
        unsigned t = atomicAdd(&g_count, 1u);
        s_last = (t == NBLOCKS - 1) ? 1u : 0u;
    }
    __syncthreads();
    if (s_last && threadIdx.x < 32) {
        volatile float* ga = g_acc;
        float v = 3.4e38f;
        for (int idx = lane; idx < NS * NS; idx += 32) v = fminf(v, ga[idx]);
        for (int idx = lane; idx < NS * NS; idx += 32) g_acc[idx] = 0.0f;  // reset
#pragma unroll
        for (int off = 16; off; off >>= 1)
            v = fminf(v, __shfl_xor_sync(0xffffffffu, v, off));
        if (lane == 0) { out[0] = v * (1.0f / COUNT_F); g_count = 0u; }
    }
}

extern "C" void kernel_launch(void* const* d_in, const int* in_sizes, int n_in,
                              void* d_out, int out_size) {
    (void)in_sizes; (void)n_in; (void)out_size;
    const float* x = (const float*)d_in[0];
    const float* y = (const float*)d_in[1];
    float* out = (float*)d_out;

    dim3 grid(2, 34, 12);
    corr_kernel<<<grid, 128>>>(x, y, out);
}

// round 15
// speedup vs baseline: 1.3319x; 1.3319x over previous
#include <cuda_runtime.h>
#include <cstdint>

// UnalignmentLoss: min over 17x17 shifts (step 2) of mean L1 between shifted
// x crop and fixed y center crop. x,y: (4,3,256,256) fp32, crop 224x224.
//
// R4-structure (empirical best): one warp per (plane, shift-row i, 8-row
// chunk); x rows prefetched in registers and staged to swizzled smem
// (conflict-free STS.128/LDS.v2.b64, one 10-granule batch -> max MLP);
// y rows prefetched in registers as pre-packed f32x2 pairs. Packed f32x2
// fma/add, abs = 64-bit AND. Separate 1-warp final kernel does the min.

#define NS    17
#define W_    256
#define TOLC  16
#define COUNT_F 602112.0f   // 4*3*224*224

__device__ float g_acc[NS * NS];   // zero at load; final_kernel restores 0

// ---- packed f32x2 helpers (uint64_t = b64 carrier) ----
__device__ __forceinline__ uint64_t f2add(uint64_t a, uint64_t b) {
    uint64_t r; asm("add.rn.f32x2 %0, %1, %2;" : "=l"(r) : "l"(a), "l"(b)); return r;
}
__device__ __forceinline__ uint64_t f2fma(uint64_t a, uint64_t b, uint64_t c) {
    uint64_t r; asm("fma.rn.f32x2 %0, %1, %2, %3;" : "=l"(r) : "l"(a), "l"(b), "l"(c)); return r;
}
__device__ __forceinline__ uint64_t f2abs(uint64_t a) {
    return a & 0x7FFFFFFF7FFFFFFFULL;
}
__device__ __forceinline__ void unpack2(uint64_t v, float& lo, float& hi) {
    asm("mov.b64 {%0, %1}, %2;" : "=f"(lo), "=f"(hi) : "l"(v));
}
__device__ __forceinline__ void sts128(unsigned addr, float4 v) {
    asm volatile("st.shared.v4.f32 [%0], {%1,%2,%3,%4};"
                 :: "r"(addr), "f"(v.x), "f"(v.y), "f"(v.z), "f"(v.w));
}
__device__ __forceinline__ void lds_2b64(unsigned addr, uint64_t& a, uint64_t& b) {
    asm volatile("ld.shared.v2.b64 {%0,%1}, [%2];" : "=l"(a), "=l"(b) : "r"(addr));
}
// XOR swizzle on 16B granule index (row = 64 granules): conflict-free for the
// 2-granule staging stores and the 10-granule strided window reads.
__device__ __forceinline__ int swz(int t) { return t ^ ((t >> 3) & 7); }

#define NEG1_X2 0xBF800000BF800000ULL   // packed (-1.0f, -1.0f)

__global__ __launch_bounds__(128) void corr_kernel(const float* __restrict__ x,
                                                   const float* __restrict__ y) {
    const int warp = threadIdx.x >> 5;
    const int lane = threadIdx.x & 31;
    const int bc   = blockIdx.z;       // plane
    const int i    = blockIdx.y;       // shift-row index (shift = 2*i)
    const int r0   = blockIdx.x * 32 + warp * 8;

    const float* xb = x + (size_t)bc * (W_ * W_);
    const float* yb = y + (size_t)bc * (W_ * W_);

    __shared__ __align__(16) float xs[4][2][W_];   // [warp][double-buffer][256]

    const unsigned base = (unsigned)__cvta_generic_to_shared(&xs[warp][0][0]);

    const int Lc = lane < 28 ? lane : 27;          // idle lanes: broadcast reads
    unsigned roff[10];
#pragma unroll
    for (int m = 0; m < 10; m++) roff[m] = (unsigned)(swz(2 * Lc + m) * 16);
    const unsigned s0 = (unsigned)(swz(2 * lane)     * 16);
    const unsigned s1 = (unsigned)(swz(2 * lane + 1) * 16);

    uint64_t acc[NS];
#pragma unroll
    for (int j = 0; j < NS; j++) acc[j] = 0ull;    // +0.0f,+0.0f

    // Prefetch row 0 of x (float4) and y (pre-packed f32x2 pairs).
    const float4* xrow = (const float4*)(xb + (size_t)(2 * i + r0) * W_);
    float4 xa = xrow[2 * lane];
    float4 xc = xrow[2 * lane + 1];
    const ulonglong2* yrow = (const ulonglong2*)(yb + (size_t)(TOLC + r0) * W_ + TOLC);
    ulonglong2 yA = yrow[2 * lane];       // pairs (y0,y1)
    ulonglong2 yB = yrow[2 * lane + 1];   // pairs (y2,y3)

#pragma unroll 1
    for (int rr = 0; rr < 8; rr++) {
        const unsigned boff = (rr & 1) ? (unsigned)(W_ * 4) : 0u;
        sts128(base + boff + s0, xa);
        sts128(base + boff + s1, xc);

        const uint64_t py0 = yA.x, py1 = yA.y, py2 = yB.x, py3 = yB.y;

        if (rr < 7) {   // prefetch next x AND y rows while this row computes
            const float4* xn = (const float4*)(xb + (size_t)(2 * i + r0 + rr + 1) * W_);
            xa = xn[2 * lane];
            xc = xn[2 * lane + 1];
            const ulonglong2* yn =
                (const ulonglong2*)(yb + (size_t)(TOLC + r0 + rr + 1) * W_ + TOLC);
            yA = yn[2 * lane];
            yB = yn[2 * lane + 1];
        }

        // Single per-row barrier: orders this row's STS before the LDS batch,
        // and (by bounding lane slip to <1 iteration) the next iteration's STS
        // to the OTHER buffer can never pass a lane still reading this one.
        __syncwarp();

        uint64_t wd[20];   // 40-float window x[8L .. 8L+40) as 20 f32x2 pairs
#pragma unroll
        for (int m = 0; m < 10; m++)
            lds_2b64(base + boff + roff[m], wd[2 * m], wd[2 * m + 1]);

#pragma unroll
        for (int j = 0; j < NS; j++) {
            uint64_t a0 = f2abs(f2fma(py0, NEG1_X2, wd[j + 0]));  // |x - y|
            uint64_t a1 = f2abs(f2fma(py1, NEG1_X2, wd[j + 1]));
            uint64_t a2 = f2abs(f2fma(py2, NEG1_X2, wd[j + 2]));
            uint64_t a3 = f2abs(f2fma(py3, NEG1_X2, wd[j + 3]));
            acc[j] = f2add(acc[j], f2add(f2add(a0, a1), f2add(a2, a3)));
        }
    }

    // Reduce: lane j keeps shift-column j's warp sum; idle lanes contribute 0.
    float keep = 0.0f;
#pragma unroll
    for (int j = 0; j < NS; j++) {
        float lo, hi; unpack2(acc[j], lo, hi);
        float v = (lane < 28) ? (lo + hi) : 0.0f;
#pragma unroll
        for (int off = 16; off; off >>= 1) v += __shfl_xor_sync(0xffffffffu, v, off);
        if (lane == j) keep = v;
    }
    if (lane < NS) atomicAdd(&g_acc[i * NS + lane], keep);
}

__global__ void final_kernel(float* __restrict__ out) {
    const int lane = threadIdx.x;
    float v = 3.4e38f;
    for (int idx = lane; idx < NS * NS; idx += 32) v = fminf(v, g_acc[idx]);
    __syncwarp();
    for (int idx = lane; idx < NS * NS; idx += 32) g_acc[idx] = 0.0f;  // reset
#pragma unroll
    for (int off = 16; off; off >>= 1)
        v = fminf(v, __shfl_xor_sync(0xffffffffu, v, off));
    if (lane == 0) out[0] = v * (1.0f / COUNT_F);
}

extern "C" void kernel_launch(void* const* d_in, const int* in_sizes, int n_in,
                              void* d_out, int out_size) {
    (void)in_sizes; (void)n_in; (void)out_size;
    const float* x = (const float*)d_in[0];
    const float* y = (const float*)d_in[1];
    float* out = (float*)d_out;

    dim3 grid(7, NS, 12);
    corr_kernel<<<grid, 128>>>(x, y);
    final_kernel<<<1, 32>>>(out);
}